// round 8
// baseline (speedup 1.0000x reference)
#include <cuda_runtime.h>

// QPSK modulator: bits (256,16384) int32 -> Gray QPSK -> x16 zero-stuff
// (offset 8) -> RRC (K=128) -> out (256, 131072, 2) float32.
//
// Polyphase: y[16q+p] = sum_{i=0..7} sym[q+jmin+i] * rrc[k0+16i],
//   k0 = (71-p)&15, jmin = (p<=7) ? -4 : -3, scaled by sqrt(16).
// Symbols are +-1/sqrt2 -> fold sqrt(16)/sqrt(2) into taps; each output is a
// sum of 8 signed taps -> 256 values per phase -> 8x256 float2 lookup table
// built once per block. Mainloop: ballot sign bits -> funnel-shift 8-bit
// pattern -> 2x LDS.64 -> streaming STG.128 (st.global.cs: the bench times
// steady-state DRAM write drain; evict-first was the R7 win).
// R8: PERSISTENT blocks (grid = 148*8 = exactly one wave). Removes 3 wave
// transitions and amortizes the table-build prologue 3.5x.

#define B_ROWS     256
#define NUM_BITS   16384
#define NS         8192
#define SPS        16
#define UP_LEN     (NS * SPS)          // 131072
#define SCALE      2.82842712474619f   // sqrt(16)/sqrt(2)

#define SYMS_PER_BLOCK   512
#define OUTS_PER_BLOCK   (SYMS_PER_BLOCK * SPS)     // 8192 complex
#define THREADS          256
#define ITS              16
#define TILES            (UP_LEN / OUTS_PER_BLOCK)  // 16
#define N_ITEMS          (TILES * B_ROWS)           // 4096
#define GRID_BLOCKS      (148 * 8)                  // one full wave
#define TROW             257                        // padded row stride
#define NWORDS           18                         // 520 sign bits

typedef unsigned long long ull;

__device__ __forceinline__ ull pack2(float lo, float hi) {
    ull v;
    asm("mov.b64 %0, {%1, %2};" : "=l"(v) : "f"(lo), "f"(hi));
    return v;
}

__device__ __forceinline__ void stcs2(ulonglong2* p, ull lo, ull hi) {
    asm volatile("st.global.cs.v2.u64 [%0], {%1, %2};"
                 :: "l"(p), "l"(lo), "l"(hi) : "memory");
}

__device__ __forceinline__ void stcs1(ull* p, ull v) {
    asm volatile("st.global.cs.u64 [%0], %1;" :: "l"(p), "l"(v) : "memory");
}

__global__ __launch_bounds__(THREADS, 8)
void qpsk_mod_kernel(const int* __restrict__ bits,
                     const float* __restrict__ rrc,
                     ulonglong2* __restrict__ out4)
{
    __shared__ __align__(16) float2 s_tab[8 * TROW];
    __shared__ unsigned s_wre[NWORDS], s_wim[NWORDS];

    const int tid = threadIdx.x;

    // ---- Build lookup table ONCE per persistent block.
    {
        const int r    = tid >> 5;          // phase-pair row 0..7
        const int ln   = tid & 31;
        const int k0e  = (71 - 2 * r) & 15; // odd
        const int k0o  = k0e - 1;
        float te[8], to[8];
        #pragma unroll
        for (int i = 0; i < 8; i++) {
            te[i] = __ldg(rrc + k0e + 16 * i) * SCALE;
            to[i] = __ldg(rrc + k0o + 16 * i) * SCALE;
        }
        #pragma unroll
        for (int j = 0; j < 8; j++) {
            int b = ln + 32 * j;
            float se = 0.f, so = 0.f;
            #pragma unroll
            for (int i = 0; i < 8; i++) {
                float sg = ((b >> i) & 1) ? -1.f : 1.f;
                se = fmaf(sg, te[i], se);
                so = fmaf(sg, to[i], so);
            }
            s_tab[r * TROW + b] = make_float2(se, so);
        }
    }

    // Per-thread mainloop constants
    const unsigned lane = tid & 31;
    const int l    = tid & 7;
    const int grp  = tid >> 3;                 // 0..31
    const int flag = (l >= 4) ? 1 : 0;         // (phase >= 8)
    const float2* tabp = s_tab + l * TROW;

    // ---- Persistent item loop: item = (row, tile)
    for (int item = blockIdx.x; item < N_ITEMS; item += GRID_BLOCKS) {
        const int tile = item & (TILES - 1);
        const int row  = item >> 4;
        const int q0   = tile * SYMS_PER_BLOCK;

        const int2* bits2 = (const int2*)(bits + (long long)row * NUM_BITS);

        // Stage sign bits via ballot: word w holds symbols 32w..32w+31
        // (local t <-> symbol g = q0-4+t; out-of-range -> +1, fixed below).
        __syncthreads();   // protect s_wre/s_wim from previous item's readers
        #pragma unroll
        for (int k = 0; k < 3; k++) {
            int t = k * THREADS + tid;
            int g = q0 - 4 + t;
            bool valid = (t < SYMS_PER_BLOCK + 8) && (g >= 0) && (g < NS);
            int2 bb = make_int2(0, 0);
            if (valid) bb = bits2[g];
            unsigned mre = __ballot_sync(0xFFFFFFFFu, valid && (bb.y & 1));
            unsigned mim = __ballot_sync(0xFFFFFFFFu, valid && (bb.x & 1));
            int wi = t >> 5;
            if (lane == 0 && wi < NWORDS) { s_wre[wi] = mre; s_wim[wi] = mim; }
        }
        __syncthreads();

        ulonglong2* out_base =
            out4 + (((long long)row * UP_LEN + (long long)tile * OUTS_PER_BLOCK) >> 1);

        #pragma unroll
        for (int it = 0; it < ITS; it++) {
            int pi = it * THREADS + tid;           // pair index 0..4095
            int w  = it * 32 + grp + flag;         // window start bit
            int wi = w >> 5, sh = w & 31;
            unsigned pre = __funnelshift_r(s_wre[wi], s_wre[wi + 1], sh) & 0xFF;
            unsigned pim = __funnelshift_r(s_wim[wi], s_wim[wi + 1], sh) & 0xFF;
            float2 vr = tabp[pre];                 // (re_even, re_odd)
            float2 vi = tabp[pim];                 // (im_even, im_odd)
            stcs2(out_base + pi, pack2(vr.x, vi.x), pack2(vr.y, vi.y));
        }

        // Edge fixup: windows touching symbols outside [0,NS) assumed +1;
        // true value uses 0. Contaminated: n<64 and n>=UP_LEN-64. Recompute.
        if (tile == 0 || tile == TILES - 1) {
            if (tid < 64) {
                int n = (tile == 0) ? tid : (UP_LEN - 64 + tid);
                int p = n & 15, q = n >> 4;
                int k0   = (71 - p) & 15;
                int jmin = (p <= 7) ? -4 : -3;
                float re = 0.f, im = 0.f;
                #pragma unroll
                for (int i = 0; i < 8; i++) {
                    int g = q + jmin + i;
                    if ((unsigned)g < (unsigned)NS) {
                        int2 bb = bits2[g];
                        float t = __ldg(rrc + k0 + 16 * i) * SCALE;
                        re += (bb.y & 1) ? -t : t;
                        im += (bb.x & 1) ? -t : t;
                    }
                }
                ull* out2 = (ull*)out4;
                stcs1(out2 + (long long)row * UP_LEN + n, pack2(re, im));
            }
        }
    }
}

extern "C" void kernel_launch(void* const* d_in, const int* in_sizes, int n_in,
                              void* d_out, int out_size)
{
    const int*   bits = (const int*)d_in[0];
    const float* rrc  = (const float*)d_in[1];
    ulonglong2*  out  = (ulonglong2*)d_out;

    qpsk_mod_kernel<<<GRID_BLOCKS, THREADS>>>(bits, rrc, out);
}